// round 15
// baseline (speedup 1.0000x reference)
#include <cuda_runtime.h>
#include <cuda_bf16.h>
#include <math_constants.h>
#include <cstdint>

#define BB   8
#define CIN  512
#define NN   4096
#define DDIM 256
#define KKE  2048
#define CAP  16
#define C0_BOUND 1.5e-4f

// ---- scratch (device globals; no allocation allowed) ----
__device__ float g_zet[BB * NN * DDIM];                // ze fp32 transposed [b][n][d]
__device__ float g_esq[KKE];                           // ||e_k||^2
__device__ float g_enorm[KKE];                         // ||e_k||
__device__ float g_znorm2[BB * NN];                    // ||ze_n||^2 (atomic accum)
__device__ float g_zsum[KKE * DDIM];                   // segment sums
__device__ float g_nsum[KKE];                          // segment counts
__device__ __nv_bfloat16 g_embb[2u * KKE * DDIM];      // emb 2-plane bf16 split
__device__ __nv_bfloat16 g_zeb[2u * BB * NN * DDIM];   // ze 2-plane split+transposed

__device__ __forceinline__ uint32_t smem_u32(const void* p) {
    uint32_t a;
    asm("{ .reg .u64 t; cvta.to.shared.u64 t, %1; cvt.u32.u64 %0, t; }" : "=r"(a) : "l"(p));
    return a;
}
__device__ __forceinline__ void ldsm_x4(uint32_t& r0, uint32_t& r1, uint32_t& r2, uint32_t& r3,
                                        uint32_t addr) {
    asm volatile("ldmatrix.sync.aligned.m8n8.x4.shared.b16 {%0,%1,%2,%3}, [%4];"
                 : "=r"(r0), "=r"(r1), "=r"(r2), "=r"(r3) : "r"(addr));
}
__device__ __forceinline__ void mma16816(float* c, const uint32_t* a, const uint32_t* b) {
    asm volatile("mma.sync.aligned.m16n8k16.row.col.f32.bf16.bf16.f32 "
                 "{%0,%1,%2,%3}, {%4,%5,%6,%7}, {%8,%9}, {%0,%1,%2,%3};"
                 : "+f"(c[0]), "+f"(c[1]), "+f"(c[2]), "+f"(c[3])
                 : "r"(a[0]), "r"(a[1]), "r"(a[2]), "r"(a[3]), "r"(b[0]), "r"(b[1]));
}
__device__ __forceinline__ uint32_t orderable(float s) {
    uint32_t u = __float_as_uint(s);
    return (u & 0x80000000u) ? ~u : (u | 0x80000000u);
}
__device__ __forceinline__ void cp_async16(uint32_t smem_addr, const void* gptr) {
    asm volatile("cp.async.cg.shared.global [%0], [%1], 16;"
                 :: "r"(smem_addr), "l"(gptr) : "memory");
}
#define CP_COMMIT() asm volatile("cp.async.commit_group;" ::: "memory")
#define CP_WAIT0()  asm volatile("cp.async.wait_group 0;" ::: "memory")

// ============================================================
// 2-plane bf16 split helper
// ============================================================
__device__ __forceinline__ void split2(float x, __nv_bfloat16& h, __nv_bfloat16& m) {
    h = __float2bfloat16(x);
    m = __float2bfloat16(x - __bfloat162float(h));
}

// ============================================================
// prep: fused esq/enorm + emb 2-plane split + zero all scatter
// buffers. One warp per codebook row; 65536 threads total.
// ============================================================
__global__ void __launch_bounds__(256) prep_kernel(const float* __restrict__ emb) {
    const int tid = blockIdx.x * blockDim.x + threadIdx.x;   // 0..65535
    const int gw = tid >> 5;                                 // 0..2047 (code row)
    const int lane = threadIdx.x & 31;

    const float* row = emb + (size_t)gw * DDIM + lane * 8;
    float4 v0 = *(const float4*)row;
    float4 v1 = *(const float4*)(row + 4);
    float s = v0.x*v0.x + v0.y*v0.y + v0.z*v0.z + v0.w*v0.w
            + v1.x*v1.x + v1.y*v1.y + v1.z*v1.z + v1.w*v1.w;

    float vals[8] = {v0.x, v0.y, v0.z, v0.w, v1.x, v1.y, v1.z, v1.w};
    uint32_t hq[4], mq[4];
#pragma unroll
    for (int p2 = 0; p2 < 4; p2++) {
        __nv_bfloat16 h0, m0, h1, m1;
        split2(vals[p2 * 2], h0, m0);
        split2(vals[p2 * 2 + 1], h1, m1);
        hq[p2] = (uint32_t)__bfloat16_as_ushort(h0) | ((uint32_t)__bfloat16_as_ushort(h1) << 16);
        mq[p2] = (uint32_t)__bfloat16_as_ushort(m0) | ((uint32_t)__bfloat16_as_ushort(m1) << 16);
    }
    const size_t eoff = (size_t)gw * DDIM + lane * 8;
    *(uint4*)&g_embb[eoff] = make_uint4(hq[0], hq[1], hq[2], hq[3]);
    *(uint4*)&g_embb[(size_t)KKE * DDIM + eoff] = make_uint4(mq[0], mq[1], mq[2], mq[3]);

#pragma unroll
    for (int off = 16; off; off >>= 1) s += __shfl_down_sync(0xffffffffu, s, off);
    if (lane == 0) { g_esq[gw] = s; g_enorm[gw] = sqrtf(s); }

    const float4 z4 = make_float4(0.f, 0.f, 0.f, 0.f);
    ((float4*)g_zsum)[tid] = z4;
    ((float4*)g_zsum)[tid + 65536] = z4;
    if (tid < 8192) ((float4*)g_znorm2)[tid] = z4;
    if (tid < 512)  ((float4*)g_nsum)[tid] = z4;
}

// ============================================================
// GEMM1 (fused): ze = W*z -> transposed fp32 g_zet, bf16
// planes g_zeb, per-column ||ze||^2 partials. (R13/R14 version)
// ============================================================
__global__ void __launch_bounds__(256, 2) gemm1_kernel(
    const float* __restrict__ z, const float* __restrict__ W)
{
    __shared__ float Ws[16][132];
    __shared__ float Zs[16][132];
    __shared__ float T[64][129];

    const int n0 = blockIdx.x * 128;
    const int d0 = blockIdx.y * 128;
    const int b  = blockIdx.z;
    const int tid = threadIdx.x;
    const int tk = tid >> 4;
    const int tn = tid & 15;

    float acc[8][8];
#pragma unroll
    for (int i = 0; i < 8; i++)
#pragma unroll
        for (int j = 0; j < 8; j++) acc[i][j] = 0.f;

    for (int c0 = 0; c0 < CIN; c0 += 16) {
#pragma unroll
        for (int i = 0; i < 8; i++) {
            int lin = tid + 256 * i;
            int dl = lin >> 4, cc = lin & 15;
            Ws[cc][dl] = W[(size_t)(d0 + dl) * CIN + c0 + cc];
        }
#pragma unroll
        for (int i = 0; i < 8; i++) {
            int lin = tid + 256 * i;
            int cc = lin >> 7, nl = lin & 127;
            Zs[cc][nl] = z[((size_t)b * CIN + c0 + cc) * NN + n0 + nl];
        }
        __syncthreads();
#pragma unroll
        for (int cc = 0; cc < 16; cc++) {
            float4 a0 = *(const float4*)&Ws[cc][tk * 8];
            float4 a1 = *(const float4*)&Ws[cc][tk * 8 + 4];
            float4 b0 = *(const float4*)&Zs[cc][tn * 8];
            float4 b1 = *(const float4*)&Zs[cc][tn * 8 + 4];
            float a[8] = {a0.x, a0.y, a0.z, a0.w, a1.x, a1.y, a1.z, a1.w};
            float bv[8] = {b0.x, b0.y, b0.z, b0.w, b1.x, b1.y, b1.z, b1.w};
#pragma unroll
            for (int i = 0; i < 8; i++)
#pragma unroll
                for (int j = 0; j < 8; j++) acc[i][j] += a[i] * bv[j];
        }
        __syncthreads();
    }

    const int nl  = tid >> 1;
    const int dof = (tid & 1) * 32;
    const size_t ZP = (size_t)BB * NN * DDIM;
    float s2tot = 0.f;

#pragma unroll 1
    for (int p = 0; p < 2; p++) {
        if (p) __syncthreads();
        if ((tk >> 3) == p) {
            const int trow0 = (tk & 7) * 8;
#pragma unroll
            for (int i = 0; i < 8; i++)
#pragma unroll
                for (int j = 0; j < 8; j++)
                    T[trow0 + i][tn * 8 + j] = acc[i][j];
        }
        __syncthreads();

        const size_t base = ((size_t)b * NN + n0 + nl) * DDIM + d0 + p * 64 + dof;
        uint32_t hq[4], mq[4];
#pragma unroll
        for (int u8 = 0; u8 < 8; u8++) {
            float4 f = make_float4(T[dof + u8 * 4 + 0][nl], T[dof + u8 * 4 + 1][nl],
                                   T[dof + u8 * 4 + 2][nl], T[dof + u8 * 4 + 3][nl]);
            *(float4*)&g_zet[base + u8 * 4] = f;
            s2tot = fmaf(f.x, f.x, s2tot); s2tot = fmaf(f.y, f.y, s2tot);
            s2tot = fmaf(f.z, f.z, s2tot); s2tot = fmaf(f.w, f.w, s2tot);
            __nv_bfloat16 h0, m0, h1, m1, h2, m2, h3, m3;
            split2(f.x, h0, m0); split2(f.y, h1, m1);
            split2(f.z, h2, m2); split2(f.w, h3, m3);
            int q = (u8 & 1) * 2;
            hq[q]     = (uint32_t)__bfloat16_as_ushort(h0) | ((uint32_t)__bfloat16_as_ushort(h1) << 16);
            hq[q + 1] = (uint32_t)__bfloat16_as_ushort(h2) | ((uint32_t)__bfloat16_as_ushort(h3) << 16);
            mq[q]     = (uint32_t)__bfloat16_as_ushort(m0) | ((uint32_t)__bfloat16_as_ushort(m1) << 16);
            mq[q + 1] = (uint32_t)__bfloat16_as_ushort(m2) | ((uint32_t)__bfloat16_as_ushort(m3) << 16);
            if (u8 & 1) {
                int e0 = (u8 >> 1) * 8;
                *(uint4*)&g_zeb[base + e0]      = make_uint4(hq[0], hq[1], hq[2], hq[3]);
                *(uint4*)&g_zeb[ZP + base + e0] = make_uint4(mq[0], mq[1], mq[2], mq[3]);
            }
        }
    }
    s2tot += __shfl_xor_sync(0xffffffffu, s2tot, 1);
    if ((tid & 1) == 0)
        atomicAdd(&g_znorm2[(size_t)b * NN + n0 + nl], s2tot);
}

// ============================================================
// MEGA pass: 3-term approx score GEMM + candidate collection
// + in-CTA exact refine + in-CTA gather/scatter.
// Stage double-buffered cp.async (A+B d-chunks), 102 KB smem,
// 2 CTAs/SM. CTA owns (b, 64 n-cols); candidates per column are
// complete within the CTA, so refine + gather run in the tail.
// ============================================================
#define STAGE_B  49152                  // A_h 16K | A_m 16K | B_h 8K | B_m 8K
#define OFF_CTRL (2 * STAGE_B)          // 98304
#define SMEM_ARG (OFF_CTRL + 6144)      // 104448

__global__ void __launch_bounds__(256, 2) argmin_mega_kernel(
    const float* __restrict__ emb, float* __restrict__ out)
{
    extern __shared__ char smem[];
    unsigned int* colthr  = (unsigned int*)(smem + OFF_CTRL);        // [64]
    unsigned int* cnt_s   = (unsigned int*)(smem + OFF_CTRL + 256);  // [64]
    float* znorm_s        = (float*)(smem + OFF_CTRL + 512);         // [64]
    float* esq_s          = (float*)(smem + OFF_CTRL + 768);         // [128]
    float* enorm_s        = (float*)(smem + OFF_CTRL + 1280);        // [128]
    unsigned int* cand_s  = (unsigned int*)(smem + OFF_CTRL + 1792); // [64*CAP]
    int* minidx_s         = (int*)(smem + OFF_CTRL + 5888);          // [64]

    const int tid = threadIdx.x;
    const int wid = tid >> 5;
    const int L   = tid & 31;
    const int n0  = blockIdx.x * 64;
    const int b   = blockIdx.y;
    const int wM  = wid >> 1;        // 0..3
    const int wN  = wid & 1;         // 0..1

    const uint32_t smem_base = smem_u32(smem);
    const size_t ZP = (size_t)BB * NN * DDIM;

    if (tid < 64) {
        colthr[tid] = 0xFFFFFFFFu;
        cnt_s[tid] = 0u;
        znorm_s[tid] = sqrtf(g_znorm2[(size_t)b * NN + n0 + tid]);
    }

    const int rowA_l = L & 15;
    const int kxA    = L >> 4;
    const int rowB_l = (L & 7) | ((L & 16) >> 1);
    const int kxB    = (L >> 3) & 1;

    auto load_stage = [&](int s) {
        const int kt = s >> 2, dch = s & 3;
        const int k0 = kt * 128;
        const uint32_t dst = smem_base + (s & 1) * STAGE_B;
#pragma unroll 4
        for (int q = 0; q < 8; q++) {          // A: 2048 granules
            int i = tid + 256 * q;
            int p = i >> 10;
            int rem = i & 1023;
            int r = rem >> 3, g = rem & 7;
            const void* src = &g_embb[((size_t)p * KKE + k0 + r) * DDIM + dch * 64 + g * 8];
            cp_async16(dst + p * 16384 + r * 128 + ((g ^ (r & 7)) * 16), src);
        }
#pragma unroll 4
        for (int q = 0; q < 4; q++) {          // B: 1024 granules
            int i = tid + 256 * q;
            int p = i >> 9;
            int rem = i & 511;
            int r = rem >> 3, g = rem & 7;
            const void* src = &g_zeb[p * ZP + ((size_t)b * NN + n0 + r) * DDIM + dch * 64 + g * 8];
            cp_async16(dst + 32768 + p * 8192 + r * 128 + ((g ^ (r & 7)) * 16), src);
        }
    };

    load_stage(0);
    CP_COMMIT();

    float acc[2][4][4];

    for (int s = 0; s < 64; s++) {
        const int kt = s >> 2, dch = s & 3;
        const int k0 = kt * 128;

        CP_WAIT0();
        __syncthreads();

        if (s + 1 < 64) { load_stage(s + 1); CP_COMMIT(); }
        if (dch == 0 && tid < 128) {
            esq_s[tid] = g_esq[k0 + tid];
            enorm_s[tid] = g_enorm[k0 + tid];
        }

        if (dch == 0) {
#pragma unroll
            for (int m = 0; m < 2; m++)
#pragma unroll
                for (int j = 0; j < 4; j++)
#pragma unroll
                    for (int r = 0; r < 4; r++) acc[m][j][r] = 0.f;
        }

        const uint32_t buf = smem_base + (s & 1) * STAGE_B;
#pragma unroll
        for (int dc = 0; dc < 4; dc++) {
            uint32_t aH[2][4], aM[2][4], bH[2][4], bM[2][4];
            {
                const int rA0 = wM * 32 + rowA_l;
                const int rA1 = rA0 + 16;
                const int gA  = dc * 2 + kxA;
                const uint32_t swA0 = ((gA ^ (rA0 & 7)) * 16);
                const uint32_t swA1 = ((gA ^ (rA1 & 7)) * 16);
                ldsm_x4(aH[0][0], aH[0][1], aH[0][2], aH[0][3], buf + rA0 * 128 + swA0);
                ldsm_x4(aH[1][0], aH[1][1], aH[1][2], aH[1][3], buf + rA1 * 128 + swA1);
                ldsm_x4(aM[0][0], aM[0][1], aM[0][2], aM[0][3], buf + 16384 + rA0 * 128 + swA0);
                ldsm_x4(aM[1][0], aM[1][1], aM[1][2], aM[1][3], buf + 16384 + rA1 * 128 + swA1);
                const int rB0 = wN * 32 + rowB_l;
                const int rB1 = rB0 + 16;
                const int gB  = dc * 2 + kxB;
                const uint32_t swB0 = ((gB ^ (rB0 & 7)) * 16);
                const uint32_t swB1 = ((gB ^ (rB1 & 7)) * 16);
                ldsm_x4(bH[0][0], bH[0][1], bH[0][2], bH[0][3], buf + 32768 + rB0 * 128 + swB0);
                ldsm_x4(bH[1][0], bH[1][1], bH[1][2], bH[1][3], buf + 32768 + rB1 * 128 + swB1);
                ldsm_x4(bM[0][0], bM[0][1], bM[0][2], bM[0][3], buf + 40960 + rB0 * 128 + swB0);
                ldsm_x4(bM[1][0], bM[1][1], bM[1][2], bM[1][3], buf + 40960 + rB1 * 128 + swB1);
            }
#pragma unroll
            for (int m = 0; m < 2; m++) {      // hh
                mma16816(acc[m][0], aH[m], &bH[0][0]);
                mma16816(acc[m][1], aH[m], &bH[0][2]);
                mma16816(acc[m][2], aH[m], &bH[1][0]);
                mma16816(acc[m][3], aH[m], &bH[1][2]);
            }
#pragma unroll
            for (int m = 0; m < 2; m++) {      // hm
                mma16816(acc[m][0], aH[m], &bM[0][0]);
                mma16816(acc[m][1], aH[m], &bM[0][2]);
                mma16816(acc[m][2], aH[m], &bM[1][0]);
                mma16816(acc[m][3], aH[m], &bM[1][2]);
            }
#pragma unroll
            for (int m = 0; m < 2; m++) {      // mh
                mma16816(acc[m][0], aM[m], &bH[0][0]);
                mma16816(acc[m][1], aM[m], &bH[0][2]);
                mma16816(acc[m][2], aM[m], &bH[1][0]);
                mma16816(acc[m][3], aM[m], &bH[1][2]);
            }
        }

        if (dch == 3) {
            // ---- epilogue Phase 1 ----
            float zn[8];
#pragma unroll
            for (int j = 0; j < 4; j++)
#pragma unroll
                for (int par = 0; par < 2; par++)
                    zn[j * 2 + par] = znorm_s[wN * 32 + j * 8 + (L & 3) * 2 + par];

            uint32_t umin[8];
#pragma unroll
            for (int c = 0; c < 8; c++) umin[c] = 0xFFFFFFFFu;

#pragma unroll
            for (int m = 0; m < 2; m++) {
                const int kl0 = wM * 32 + m * 16 + (L >> 2);
                const int kl1 = kl0 + 8;
                const float e0 = esq_s[kl0], e1 = esq_s[kl1];
                const float en0 = C0_BOUND * enorm_s[kl0], en1 = C0_BOUND * enorm_s[kl1];
#pragma unroll
                for (int j = 0; j < 4; j++)
#pragma unroll
                    for (int r = 0; r < 4; r++) {
                        const int kh = r >> 1, par = r & 1;
                        float sc = fmaf(-2.f, acc[m][j][r], kh ? e1 : e0);
                        acc[m][j][r] = sc;
                        float E = (kh ? en1 : en0) * zn[j * 2 + par];
                        uint32_t u = orderable(sc + E);
                        if (u < umin[j * 2 + par]) umin[j * 2 + par] = u;
                    }
            }
#pragma unroll
            for (int c = 0; c < 8; c++) {
#pragma unroll
                for (int off = 4; off <= 16; off <<= 1) {
                    uint32_t o = __shfl_xor_sync(0xffffffffu, umin[c], off);
                    if (o < umin[c]) umin[c] = o;
                }
            }
            if (L < 4) {
#pragma unroll
                for (int c = 0; c < 8; c++)
                    atomicMin(&colthr[wN * 32 + (c >> 1) * 8 + L * 2 + (c & 1)], umin[c]);
            }
            __syncthreads();

            // ---- epilogue Phase 2 ----
#pragma unroll
            for (int m = 0; m < 2; m++) {
                const int kl0 = wM * 32 + m * 16 + (L >> 2);
                const int kl1 = kl0 + 8;
                const float en0 = C0_BOUND * enorm_s[kl0], en1 = C0_BOUND * enorm_s[kl1];
#pragma unroll
                for (int j = 0; j < 4; j++)
#pragma unroll
                    for (int r = 0; r < 4; r++) {
                        const int kh = r >> 1, par = r & 1;
                        const int col = wN * 32 + j * 8 + (L & 3) * 2 + par;
                        float sc = acc[m][j][r];
                        float E = (kh ? en1 : en0) * zn[j * 2 + par];
                        if (orderable(sc - E) <= colthr[col]) {
                            unsigned pos = atomicAdd(&cnt_s[col], 1u);
                            if (pos < CAP)
                                cand_s[col * CAP + pos] = (unsigned)(k0 + (kh ? kl1 : kl0));
                        }
                    }
            }
        }
    }
    __syncthreads();   // candidates final; stage buffers free

    // ======== in-CTA TAIL ========
    // ---- stage fp32 ze tile into smem [64][257] (coalesced) ----
    float* zs = (float*)smem;
#pragma unroll 1
    for (int q = 0; q < 16; q++) {
        int i = tid + 256 * q;               // 0..4095 float4 units
        int r = i >> 6, c4 = i & 63;
        float4 v = *(const float4*)&g_zet[((size_t)b * NN + n0 + r) * DDIM + c4 * 4];
        zs[r * 257 + c4 * 4 + 0] = v.x; zs[r * 257 + c4 * 4 + 1] = v.y;
        zs[r * 257 + c4 * 4 + 2] = v.z; zs[r * 257 + c4 * 4 + 3] = v.w;
    }
    __syncthreads();

    // ---- exact refine: warp per 8 columns ----
#pragma unroll 1
    for (int c8 = 0; c8 < 8; c8++) {
        const int col = wid * 8 + c8;
        const float* zrow = zs + col * 257;
        const float z0x = zrow[L * 8 + 0], z0y = zrow[L * 8 + 1];
        const float z0z = zrow[L * 8 + 2], z0w = zrow[L * 8 + 3];
        const float z1x = zrow[L * 8 + 4], z1y = zrow[L * 8 + 5];
        const float z1z = zrow[L * 8 + 6], z1w = zrow[L * 8 + 7];
        const unsigned cnt = cnt_s[col];
        unsigned long long best = 0xFFFFFFFFFFFFFFFFull;

        if (cnt <= CAP) {
#pragma unroll 1
            for (unsigned i = 0; i < cnt; i++) {
                const unsigned k = cand_s[col * CAP + i];
                const float* er = emb + (size_t)k * DDIM;
                float4 e0 = *(const float4*)(er + L * 8);
                float4 e1 = *(const float4*)(er + L * 8 + 4);
                float d = e0.x * z0x;
                d = fmaf(e0.y, z0y, d); d = fmaf(e0.z, z0z, d); d = fmaf(e0.w, z0w, d);
                d = fmaf(e1.x, z1x, d); d = fmaf(e1.y, z1y, d);
                d = fmaf(e1.z, z1z, d); d = fmaf(e1.w, z1w, d);
#pragma unroll
                for (int off = 16; off; off >>= 1) d += __shfl_xor_sync(0xffffffffu, d, off);
                float sv = fmaf(-2.f, d, g_esq[k]);
                unsigned long long pk = ((unsigned long long)orderable(sv) << 32) | k;
                if (pk < best) best = pk;
            }
        } else {
            // overflow fallback: exact scan of all codes, lane-strided
#pragma unroll 1
            for (int k = L; k < KKE; k += 32) {
                const float* er = emb + (size_t)k * DDIM;
                float d = 0.f;
#pragma unroll 8
                for (int v = 0; v < 64; v++) {
                    float4 e4 = *(const float4*)(er + v * 4);
                    d = fmaf(e4.x, zrow[v * 4 + 0], d); d = fmaf(e4.y, zrow[v * 4 + 1], d);
                    d = fmaf(e4.z, zrow[v * 4 + 2], d); d = fmaf(e4.w, zrow[v * 4 + 3], d);
                }
                float sv = fmaf(-2.f, d, g_esq[k]);
                unsigned long long pk = ((unsigned long long)orderable(sv) << 32) | (unsigned)k;
                if (pk < best) best = pk;
            }
#pragma unroll
            for (int off = 16; off; off >>= 1) {
                unsigned long long o = __shfl_xor_sync(0xffffffffu, best, off);
                if (o < best) best = o;
            }
        }
        if (L == 0) minidx_s[col] = (int)(best & 0xFFFFFFFFull);
    }
    __syncthreads();

    // ---- gather zq -> out, scatter-add ze into zsum/nsum ----
    {
        const int txn = tid & 63;           // column within tile
        const int typ = tid >> 6;           // 0..3 d-phase
        const int idx = minidx_s[txn];
        const int n = n0 + txn;
#pragma unroll 4
        for (int d = typ; d < DDIM; d += 4) {
            float zev = zs[txn * 257 + d];
            out[((size_t)b * DDIM + d) * NN + n] = emb[(size_t)idx * DDIM + d];
            atomicAdd(&g_zsum[(size_t)idx * DDIM + d], zev);
        }
        if (typ == 0) atomicAdd(&g_nsum[idx], 1.0f);
    }
}

// ============================================================
// EMA finalize -> tail of d_out
// ============================================================
__global__ void ema_kernel(const float* __restrict__ ema_numer,
                           const float* __restrict__ ema_denom,
                           float* __restrict__ out)
{
    const size_t OUT_OFF = (size_t)BB * DDIM * NN;
    int i = blockIdx.x * blockDim.x + threadIdx.x;
    if (i < KKE * DDIM)
        out[OUT_OFF + i] = 0.99f * ema_numer[i] + 0.01f * g_zsum[i];
    if (i < KKE)
        out[OUT_OFF + (size_t)KKE * DDIM + i] = 0.99f * ema_denom[i] + 0.01f * g_nsum[i];
}

// ============================================================
extern "C" void kernel_launch(void* const* d_in, const int* in_sizes, int n_in,
                              void* d_out, int out_size)
{
    const float* z         = (const float*)d_in[0];
    const float* W         = (const float*)d_in[1];
    const float* emb       = (const float*)d_in[2];
    const float* ema_numer = (const float*)d_in[3];
    const float* ema_denom = (const float*)d_in[4];
    float* out = (float*)d_out;
    (void)in_sizes; (void)n_in; (void)out_size;

    cudaFuncSetAttribute(argmin_mega_kernel,
                         cudaFuncAttributeMaxDynamicSharedMemorySize, SMEM_ARG);

    // 1. fused prep: esq/enorm + emb split + zero scatter buffers
    prep_kernel<<<256, 256>>>(emb);

    // 2. fused GEMM1 (8x8): transposed fp32/bf16 planes + znorm2
    {
        dim3 grid(NN / 128, DDIM / 128, BB);
        gemm1_kernel<<<grid, 256>>>(z, W);
    }

    // 3. MEGA: approx GEMM + candidates + exact refine + gather/scatter
    {
        dim3 grid(NN / 64, BB);
        argmin_mega_kernel<<<grid, 256, SMEM_ARG>>>(emb, out);
    }

    // 4. EMA blend
    ema_kernel<<<(KKE * DDIM + 255) / 256, 256>>>(ema_numer, ema_denom, out);
}

// round 16
// speedup vs baseline: 1.0382x; 1.0382x over previous
#include <cuda_runtime.h>
#include <cuda_bf16.h>
#include <math_constants.h>
#include <cstdint>

#define BB   8
#define CIN  512
#define NN   4096
#define DDIM 256
#define KKE  2048
#define CAP  16
#define C0_BOUND 1.5e-4f

// ---- scratch (device globals; no allocation allowed) ----
__device__ float g_zet[BB * NN * DDIM];                // ze fp32 transposed [b][n][d]
__device__ float g_esq[KKE];                           // ||e_k||^2
__device__ float g_enorm[KKE];                         // ||e_k||
__device__ float g_znorm2p[2][BB * NN];                // ||ze_n||^2 partials (per d-half)
__device__ int   g_minidx[BB * NN];                    // argmin indices
__device__ float g_zsum[KKE * DDIM];                   // segment sums
__device__ float g_nsum[KKE];                          // segment counts
__device__ __nv_bfloat16 g_embb[2u * KKE * DDIM];      // emb 2-plane bf16 split
__device__ __nv_bfloat16 g_zeb[2u * BB * NN * DDIM];   // ze 2-plane split+transposed
__device__ unsigned int g_cand[(size_t)BB * NN * CAP]; // candidate lists
__device__ unsigned int g_ccnt[BB * NN];               // candidate counts

__device__ __forceinline__ uint32_t smem_u32(const void* p) {
    uint32_t a;
    asm("{ .reg .u64 t; cvta.to.shared.u64 t, %1; cvt.u32.u64 %0, t; }" : "=r"(a) : "l"(p));
    return a;
}
__device__ __forceinline__ void ldsm_x4(uint32_t& r0, uint32_t& r1, uint32_t& r2, uint32_t& r3,
                                        uint32_t addr) {
    asm volatile("ldmatrix.sync.aligned.m8n8.x4.shared.b16 {%0,%1,%2,%3}, [%4];"
                 : "=r"(r0), "=r"(r1), "=r"(r2), "=r"(r3) : "r"(addr));
}
__device__ __forceinline__ void mma16816(float* c, const uint32_t* a, const uint32_t* b) {
    asm volatile("mma.sync.aligned.m16n8k16.row.col.f32.bf16.bf16.f32 "
                 "{%0,%1,%2,%3}, {%4,%5,%6,%7}, {%8,%9}, {%0,%1,%2,%3};"
                 : "+f"(c[0]), "+f"(c[1]), "+f"(c[2]), "+f"(c[3])
                 : "r"(a[0]), "r"(a[1]), "r"(a[2]), "r"(a[3]), "r"(b[0]), "r"(b[1]));
}
__device__ __forceinline__ uint32_t orderable(float s) {
    uint32_t u = __float_as_uint(s);
    return (u & 0x80000000u) ? ~u : (u | 0x80000000u);
}
__device__ __forceinline__ void cp_async16(uint32_t smem_addr, const void* gptr) {
    asm volatile("cp.async.cg.shared.global [%0], [%1], 16;"
                 :: "r"(smem_addr), "l"(gptr) : "memory");
}
#define CP_COMMIT() asm volatile("cp.async.commit_group;" ::: "memory")
#define CP_WAIT0()  asm volatile("cp.async.wait_group 0;" ::: "memory")

// ============================================================
// 2-plane bf16 split helper
// ============================================================
__device__ __forceinline__ void split2(float x, __nv_bfloat16& h, __nv_bfloat16& m) {
    h = __float2bfloat16(x);
    m = __float2bfloat16(x - __bfloat162float(h));
}

// ============================================================
// GEMM1 (fused, v3): prep (emb split + esq/enorm + zero zsum/
// nsum) folded into the first 256 blocks, then ze = W*z ->
// transposed fp32 g_zet, bf16 planes g_zeb, per-column
// ||ze||^2 partial stored to g_znorm2p[by] (no atomics).
// Block 128d x 128n, 256 threads, 8d x 8n each.
// ============================================================
__global__ void __launch_bounds__(256, 2) gemm1_kernel(
    const float* __restrict__ z, const float* __restrict__ W,
    const float* __restrict__ emb)
{
    __shared__ float Ws[16][132];
    __shared__ float Zs[16][132];
    __shared__ float T[64][129];

    const int n0 = blockIdx.x * 128;
    const int d0 = blockIdx.y * 128;
    const int b  = blockIdx.z;
    const int tid = threadIdx.x;
    const int tk = tid >> 4;
    const int tn = tid & 15;

    // ---- folded prep: first 256 blocks handle emb split + norms + zeroing ----
    {
        const int lb = blockIdx.x + 32 * (blockIdx.y + 2 * blockIdx.z);  // 0..511
        if (lb < 256) {
            const int glb = lb * 256 + tid;          // 0..65535
            const int gw = glb >> 5;                 // code row
            const int lane = tid & 31;

            const float* row = emb + (size_t)gw * DDIM + lane * 8;
            float4 v0 = *(const float4*)row;
            float4 v1 = *(const float4*)(row + 4);
            float s = v0.x*v0.x + v0.y*v0.y + v0.z*v0.z + v0.w*v0.w
                    + v1.x*v1.x + v1.y*v1.y + v1.z*v1.z + v1.w*v1.w;

            float vals[8] = {v0.x, v0.y, v0.z, v0.w, v1.x, v1.y, v1.z, v1.w};
            uint32_t hq[4], mq[4];
#pragma unroll
            for (int p2 = 0; p2 < 4; p2++) {
                __nv_bfloat16 h0, m0, h1, m1;
                split2(vals[p2 * 2], h0, m0);
                split2(vals[p2 * 2 + 1], h1, m1);
                hq[p2] = (uint32_t)__bfloat16_as_ushort(h0) | ((uint32_t)__bfloat16_as_ushort(h1) << 16);
                mq[p2] = (uint32_t)__bfloat16_as_ushort(m0) | ((uint32_t)__bfloat16_as_ushort(m1) << 16);
            }
            const size_t eoff = (size_t)gw * DDIM + lane * 8;
            *(uint4*)&g_embb[eoff] = make_uint4(hq[0], hq[1], hq[2], hq[3]);
            *(uint4*)&g_embb[(size_t)KKE * DDIM + eoff] = make_uint4(mq[0], mq[1], mq[2], mq[3]);

#pragma unroll
            for (int off = 16; off; off >>= 1) s += __shfl_down_sync(0xffffffffu, s, off);
            if (lane == 0) { g_esq[gw] = s; g_enorm[gw] = sqrtf(s); }

            const float4 z4 = make_float4(0.f, 0.f, 0.f, 0.f);
            ((float4*)g_zsum)[glb] = z4;
            ((float4*)g_zsum)[glb + 65536] = z4;
            if (glb < 512) ((float4*)g_nsum)[glb] = z4;
        }
    }

    float acc[8][8];
#pragma unroll
    for (int i = 0; i < 8; i++)
#pragma unroll
        for (int j = 0; j < 8; j++) acc[i][j] = 0.f;

    for (int c0 = 0; c0 < CIN; c0 += 16) {
#pragma unroll
        for (int i = 0; i < 8; i++) {
            int lin = tid + 256 * i;
            int dl = lin >> 4, cc = lin & 15;
            Ws[cc][dl] = W[(size_t)(d0 + dl) * CIN + c0 + cc];
        }
#pragma unroll
        for (int i = 0; i < 8; i++) {
            int lin = tid + 256 * i;
            int cc = lin >> 7, nl = lin & 127;
            Zs[cc][nl] = z[((size_t)b * CIN + c0 + cc) * NN + n0 + nl];
        }
        __syncthreads();
#pragma unroll
        for (int cc = 0; cc < 16; cc++) {
            float4 a0 = *(const float4*)&Ws[cc][tk * 8];
            float4 a1 = *(const float4*)&Ws[cc][tk * 8 + 4];
            float4 b0 = *(const float4*)&Zs[cc][tn * 8];
            float4 b1 = *(const float4*)&Zs[cc][tn * 8 + 4];
            float a[8] = {a0.x, a0.y, a0.z, a0.w, a1.x, a1.y, a1.z, a1.w};
            float bv[8] = {b0.x, b0.y, b0.z, b0.w, b1.x, b1.y, b1.z, b1.w};
#pragma unroll
            for (int i = 0; i < 8; i++)
#pragma unroll
                for (int j = 0; j < 8; j++) acc[i][j] += a[i] * bv[j];
        }
        __syncthreads();
    }

    const int nl  = tid >> 1;
    const int dof = (tid & 1) * 32;
    const size_t ZP = (size_t)BB * NN * DDIM;
    float s2tot = 0.f;

#pragma unroll 1
    for (int p = 0; p < 2; p++) {
        if (p) __syncthreads();
        if ((tk >> 3) == p) {
            const int trow0 = (tk & 7) * 8;
#pragma unroll
            for (int i = 0; i < 8; i++)
#pragma unroll
                for (int j = 0; j < 8; j++)
                    T[trow0 + i][tn * 8 + j] = acc[i][j];
        }
        __syncthreads();

        const size_t base = ((size_t)b * NN + n0 + nl) * DDIM + d0 + p * 64 + dof;
        uint32_t hq[4], mq[4];
#pragma unroll
        for (int u8 = 0; u8 < 8; u8++) {
            float4 f = make_float4(T[dof + u8 * 4 + 0][nl], T[dof + u8 * 4 + 1][nl],
                                   T[dof + u8 * 4 + 2][nl], T[dof + u8 * 4 + 3][nl]);
            *(float4*)&g_zet[base + u8 * 4] = f;
            s2tot = fmaf(f.x, f.x, s2tot); s2tot = fmaf(f.y, f.y, s2tot);
            s2tot = fmaf(f.z, f.z, s2tot); s2tot = fmaf(f.w, f.w, s2tot);
            __nv_bfloat16 h0, m0, h1, m1, h2, m2, h3, m3;
            split2(f.x, h0, m0); split2(f.y, h1, m1);
            split2(f.z, h2, m2); split2(f.w, h3, m3);
            int q = (u8 & 1) * 2;
            hq[q]     = (uint32_t)__bfloat16_as_ushort(h0) | ((uint32_t)__bfloat16_as_ushort(h1) << 16);
            hq[q + 1] = (uint32_t)__bfloat16_as_ushort(h2) | ((uint32_t)__bfloat16_as_ushort(h3) << 16);
            mq[q]     = (uint32_t)__bfloat16_as_ushort(m0) | ((uint32_t)__bfloat16_as_ushort(m1) << 16);
            mq[q + 1] = (uint32_t)__bfloat16_as_ushort(m2) | ((uint32_t)__bfloat16_as_ushort(m3) << 16);
            if (u8 & 1) {
                int e0 = (u8 >> 1) * 8;
                *(uint4*)&g_zeb[base + e0]      = make_uint4(hq[0], hq[1], hq[2], hq[3]);
                *(uint4*)&g_zeb[ZP + base + e0] = make_uint4(mq[0], mq[1], mq[2], mq[3]);
            }
        }
    }
    s2tot += __shfl_xor_sync(0xffffffffu, s2tot, 1);
    if ((tid & 1) == 0)
        g_znorm2p[blockIdx.y][(size_t)b * NN + n0 + nl] = s2tot;   // pure store, no atomic
}

// ============================================================
// Pass A: 3-term approx score GEMM + candidate collection.
// Per-granule fragment dedup (32 LDSM/stage), double-buffered
// cp.async A+B stages, 102 KB smem, 2 CTAs/SM. (R14 version)
// ============================================================
#define STAGE_B  49152                  // A_h 16K | A_m 16K | B_h 8K | B_m 8K
#define OFF_CTRL (2 * STAGE_B)          // 98304
#define SMEM_ARG (OFF_CTRL + 6144)      // 104448

__global__ void __launch_bounds__(256, 2) argmin_approx_kernel()
{
    extern __shared__ char smem[];
    unsigned int* colthr  = (unsigned int*)(smem + OFF_CTRL);        // [64]
    unsigned int* cnt_s   = (unsigned int*)(smem + OFF_CTRL + 256);  // [64]
    float* znorm_s        = (float*)(smem + OFF_CTRL + 512);         // [64]
    float* esq_s          = (float*)(smem + OFF_CTRL + 768);         // [128]
    float* enorm_s        = (float*)(smem + OFF_CTRL + 1280);        // [128]
    unsigned int* cand_s  = (unsigned int*)(smem + OFF_CTRL + 1792); // [64*CAP]

    const int tid = threadIdx.x;
    const int wid = tid >> 5;
    const int L   = tid & 31;
    const int n0  = blockIdx.x * 64;
    const int b   = blockIdx.y;
    const int wM  = wid >> 1;        // 0..3
    const int wN  = wid & 1;         // 0..1

    const uint32_t smem_base = smem_u32(smem);
    const size_t ZP = (size_t)BB * NN * DDIM;

    if (tid < 64) {
        colthr[tid] = 0xFFFFFFFFu;
        cnt_s[tid] = 0u;
        const size_t ci = (size_t)b * NN + n0 + tid;
        znorm_s[tid] = sqrtf(g_znorm2p[0][ci] + g_znorm2p[1][ci]);
    }

    const int rowA_l = L & 15;
    const int kxA    = L >> 4;
    const int rowB_l = (L & 7) | ((L & 16) >> 1);
    const int kxB    = (L >> 3) & 1;

    auto load_stage = [&](int s) {
        const int kt = s >> 2, dch = s & 3;
        const int k0 = kt * 128;
        const uint32_t dst = smem_base + (s & 1) * STAGE_B;
#pragma unroll 4
        for (int q = 0; q < 8; q++) {          // A: 2048 granules
            int i = tid + 256 * q;
            int p = i >> 10;
            int rem = i & 1023;
            int r = rem >> 3, g = rem & 7;
            const void* src = &g_embb[((size_t)p * KKE + k0 + r) * DDIM + dch * 64 + g * 8];
            cp_async16(dst + p * 16384 + r * 128 + ((g ^ (r & 7)) * 16), src);
        }
#pragma unroll 4
        for (int q = 0; q < 4; q++) {          // B: 1024 granules
            int i = tid + 256 * q;
            int p = i >> 9;
            int rem = i & 511;
            int r = rem >> 3, g = rem & 7;
            const void* src = &g_zeb[p * ZP + ((size_t)b * NN + n0 + r) * DDIM + dch * 64 + g * 8];
            cp_async16(dst + 32768 + p * 8192 + r * 128 + ((g ^ (r & 7)) * 16), src);
        }
    };

    load_stage(0);
    CP_COMMIT();

    float acc[2][4][4];

    for (int s = 0; s < 64; s++) {
        const int kt = s >> 2, dch = s & 3;
        const int k0 = kt * 128;

        CP_WAIT0();
        __syncthreads();

        if (s + 1 < 64) { load_stage(s + 1); CP_COMMIT(); }
        if (dch == 0 && tid < 128) {
            esq_s[tid] = g_esq[k0 + tid];
            enorm_s[tid] = g_enorm[k0 + tid];
        }

        if (dch == 0) {
#pragma unroll
            for (int m = 0; m < 2; m++)
#pragma unroll
                for (int j = 0; j < 4; j++)
#pragma unroll
                    for (int r = 0; r < 4; r++) acc[m][j][r] = 0.f;
        }

        const uint32_t buf = smem_base + (s & 1) * STAGE_B;
#pragma unroll
        for (int dc = 0; dc < 4; dc++) {
            uint32_t aH[2][4], aM[2][4], bH[2][4], bM[2][4];
            {
                const int rA0 = wM * 32 + rowA_l;
                const int rA1 = rA0 + 16;
                const int gA  = dc * 2 + kxA;
                const uint32_t swA0 = ((gA ^ (rA0 & 7)) * 16);
                const uint32_t swA1 = ((gA ^ (rA1 & 7)) * 16);
                ldsm_x4(aH[0][0], aH[0][1], aH[0][2], aH[0][3], buf + rA0 * 128 + swA0);
                ldsm_x4(aH[1][0], aH[1][1], aH[1][2], aH[1][3], buf + rA1 * 128 + swA1);
                ldsm_x4(aM[0][0], aM[0][1], aM[0][2], aM[0][3], buf + 16384 + rA0 * 128 + swA0);
                ldsm_x4(aM[1][0], aM[1][1], aM[1][2], aM[1][3], buf + 16384 + rA1 * 128 + swA1);
                const int rB0 = wN * 32 + rowB_l;
                const int rB1 = rB0 + 16;
                const int gB  = dc * 2 + kxB;
                const uint32_t swB0 = ((gB ^ (rB0 & 7)) * 16);
                const uint32_t swB1 = ((gB ^ (rB1 & 7)) * 16);
                ldsm_x4(bH[0][0], bH[0][1], bH[0][2], bH[0][3], buf + 32768 + rB0 * 128 + swB0);
                ldsm_x4(bH[1][0], bH[1][1], bH[1][2], bH[1][3], buf + 32768 + rB1 * 128 + swB1);
                ldsm_x4(bM[0][0], bM[0][1], bM[0][2], bM[0][3], buf + 40960 + rB0 * 128 + swB0);
                ldsm_x4(bM[1][0], bM[1][1], bM[1][2], bM[1][3], buf + 40960 + rB1 * 128 + swB1);
            }
#pragma unroll
            for (int m = 0; m < 2; m++) {      // hh
                mma16816(acc[m][0], aH[m], &bH[0][0]);
                mma16816(acc[m][1], aH[m], &bH[0][2]);
                mma16816(acc[m][2], aH[m], &bH[1][0]);
                mma16816(acc[m][3], aH[m], &bH[1][2]);
            }
#pragma unroll
            for (int m = 0; m < 2; m++) {      // hm
                mma16816(acc[m][0], aH[m], &bM[0][0]);
                mma16816(acc[m][1], aH[m], &bM[0][2]);
                mma16816(acc[m][2], aH[m], &bM[1][0]);
                mma16816(acc[m][3], aH[m], &bM[1][2]);
            }
#pragma unroll
            for (int m = 0; m < 2; m++) {      // mh
                mma16816(acc[m][0], aM[m], &bH[0][0]);
                mma16816(acc[m][1], aM[m], &bH[0][2]);
                mma16816(acc[m][2], aM[m], &bH[1][0]);
                mma16816(acc[m][3], aM[m], &bH[1][2]);
            }
        }

        if (dch == 3) {
            // ---- epilogue Phase 1 ----
            float zn[8];
#pragma unroll
            for (int j = 0; j < 4; j++)
#pragma unroll
                for (int par = 0; par < 2; par++)
                    zn[j * 2 + par] = znorm_s[wN * 32 + j * 8 + (L & 3) * 2 + par];

            uint32_t umin[8];
#pragma unroll
            for (int c = 0; c < 8; c++) umin[c] = 0xFFFFFFFFu;

#pragma unroll
            for (int m = 0; m < 2; m++) {
                const int kl0 = wM * 32 + m * 16 + (L >> 2);
                const int kl1 = kl0 + 8;
                const float e0 = esq_s[kl0], e1 = esq_s[kl1];
                const float en0 = C0_BOUND * enorm_s[kl0], en1 = C0_BOUND * enorm_s[kl1];
#pragma unroll
                for (int j = 0; j < 4; j++)
#pragma unroll
                    for (int r = 0; r < 4; r++) {
                        const int kh = r >> 1, par = r & 1;
                        float sc = fmaf(-2.f, acc[m][j][r], kh ? e1 : e0);
                        acc[m][j][r] = sc;
                        float E = (kh ? en1 : en0) * zn[j * 2 + par];
                        uint32_t u = orderable(sc + E);
                        if (u < umin[j * 2 + par]) umin[j * 2 + par] = u;
                    }
            }
#pragma unroll
            for (int c = 0; c < 8; c++) {
#pragma unroll
                for (int off = 4; off <= 16; off <<= 1) {
                    uint32_t o = __shfl_xor_sync(0xffffffffu, umin[c], off);
                    if (o < umin[c]) umin[c] = o;
                }
            }
            if (L < 4) {
#pragma unroll
                for (int c = 0; c < 8; c++)
                    atomicMin(&colthr[wN * 32 + (c >> 1) * 8 + L * 2 + (c & 1)], umin[c]);
            }
            __syncthreads();

            // ---- epilogue Phase 2 ----
#pragma unroll
            for (int m = 0; m < 2; m++) {
                const int kl0 = wM * 32 + m * 16 + (L >> 2);
                const int kl1 = kl0 + 8;
                const float en0 = C0_BOUND * enorm_s[kl0], en1 = C0_BOUND * enorm_s[kl1];
#pragma unroll
                for (int j = 0; j < 4; j++)
#pragma unroll
                    for (int r = 0; r < 4; r++) {
                        const int kh = r >> 1, par = r & 1;
                        const int col = wN * 32 + j * 8 + (L & 3) * 2 + par;
                        float sc = acc[m][j][r];
                        float E = (kh ? en1 : en0) * zn[j * 2 + par];
                        if (orderable(sc - E) <= colthr[col]) {
                            unsigned pos = atomicAdd(&cnt_s[col], 1u);
                            if (pos < CAP)
                                cand_s[col * CAP + pos] = (unsigned)(k0 + (kh ? kl1 : kl0));
                        }
                    }
            }
        }
    }
    __syncthreads();
    if (tid < 64) g_ccnt[(size_t)b * NN + n0 + tid] = cnt_s[tid];
#pragma unroll
    for (int q = 0; q < 4; q++) {
        int i = tid + 256 * q;
        int lc = i >> 4, slot = i & 15;
        g_cand[((size_t)b * NN + n0 + lc) * CAP + slot] = cand_s[i];
    }
}

// ============================================================
// Pass B: exact fp32 refinement. One warp per column.
// ============================================================
__global__ void refine_kernel(const float* __restrict__ emb) {
    const int wid = threadIdx.x >> 5;
    const int L = threadIdx.x & 31;
    const int n = blockIdx.x * 8 + wid;
    const int b = blockIdx.y;
    const size_t cidx = (size_t)b * NN + n;
    const float* zr = g_zet + cidx * DDIM;

    const float4 z0 = *(const float4*)(zr + L * 8);
    const float4 z1 = *(const float4*)(zr + L * 8 + 4);

    const unsigned cnt = g_ccnt[cidx];
    unsigned long long best = 0xFFFFFFFFFFFFFFFFull;

    if (cnt <= CAP) {
        for (unsigned i = 0; i < cnt; i++) {
            const unsigned k = g_cand[cidx * CAP + i];
            const float* er = emb + (size_t)k * DDIM;
            float4 e0 = *(const float4*)(er + L * 8);
            float4 e1 = *(const float4*)(er + L * 8 + 4);
            float d = e0.x*z0.x;
            d = fmaf(e0.y, z0.y, d); d = fmaf(e0.z, z0.z, d); d = fmaf(e0.w, z0.w, d);
            d = fmaf(e1.x, z1.x, d); d = fmaf(e1.y, z1.y, d);
            d = fmaf(e1.z, z1.z, d); d = fmaf(e1.w, z1.w, d);
#pragma unroll
            for (int off = 16; off; off >>= 1) d += __shfl_xor_sync(0xffffffffu, d, off);
            float s = fmaf(-2.f, d, g_esq[k]);
            unsigned long long pk = ((unsigned long long)orderable(s) << 32) | k;
            if (pk < best) best = pk;
        }
    } else {
        for (int k = L; k < KKE; k += 32) {
            const float* er = emb + (size_t)k * DDIM;
            float d = 0.f;
#pragma unroll 8
            for (int v = 0; v < 64; v++) {
                float4 e4 = *(const float4*)(er + v * 4);
                float4 z4 = *(const float4*)(zr + v * 4);
                d = fmaf(e4.x, z4.x, d); d = fmaf(e4.y, z4.y, d);
                d = fmaf(e4.z, z4.z, d); d = fmaf(e4.w, z4.w, d);
            }
            float s = fmaf(-2.f, d, g_esq[k]);
            unsigned long long pk = ((unsigned long long)orderable(s) << 32) | (unsigned)k;
            if (pk < best) best = pk;
        }
#pragma unroll
        for (int off = 16; off; off >>= 1) {
            unsigned long long o = __shfl_xor_sync(0xffffffffu, best, off);
            if (o < best) best = o;
        }
    }
    if (L == 0) g_minidx[cidx] = (int)(best & 0xFFFFFFFFull);
}

// ============================================================
// gather zq -> out, scatter-add ze into z_sum / n_sum.
// ============================================================
__global__ void gs_kernel(const float* __restrict__ emb, float* __restrict__ out)
{
    __shared__ float zs[32][257];
    const int b  = blockIdx.y;
    const int n0 = blockIdx.x * 32;
    const int tx = threadIdx.x;
    const int ty = threadIdx.y;
    const int tid = ty * 32 + tx;

#pragma unroll
    for (int q = 0; q < 8; q++) {
        int i = tid + 256 * q;
        int r = i >> 6, c4 = i & 63;
        float4 v = *(const float4*)&g_zet[((size_t)b * NN + n0 + r) * DDIM + c4 * 4];
        zs[r][c4 * 4 + 0] = v.x; zs[r][c4 * 4 + 1] = v.y;
        zs[r][c4 * 4 + 2] = v.z; zs[r][c4 * 4 + 3] = v.w;
    }
    __syncthreads();

    const int n = n0 + tx;
    const int idx = g_minidx[(size_t)b * NN + n];
#pragma unroll 4
    for (int d = ty; d < DDIM; d += 8) {
        float zev = zs[tx][d];
        out[((size_t)b * DDIM + d) * NN + n] = emb[(size_t)idx * DDIM + d];
        atomicAdd(&g_zsum[(size_t)idx * DDIM + d], zev);
    }
    if (ty == 0) atomicAdd(&g_nsum[idx], 1.0f);
}

// ============================================================
// EMA finalize -> tail of d_out
// ============================================================
__global__ void ema_kernel(const float* __restrict__ ema_numer,
                           const float* __restrict__ ema_denom,
                           float* __restrict__ out)
{
    const size_t OUT_OFF = (size_t)BB * DDIM * NN;
    int i = blockIdx.x * blockDim.x + threadIdx.x;
    if (i < KKE * DDIM)
        out[OUT_OFF + i] = 0.99f * ema_numer[i] + 0.01f * g_zsum[i];
    if (i < KKE)
        out[OUT_OFF + (size_t)KKE * DDIM + i] = 0.99f * ema_denom[i] + 0.01f * g_nsum[i];
}

// ============================================================
extern "C" void kernel_launch(void* const* d_in, const int* in_sizes, int n_in,
                              void* d_out, int out_size)
{
    const float* z         = (const float*)d_in[0];
    const float* W         = (const float*)d_in[1];
    const float* emb       = (const float*)d_in[2];
    const float* ema_numer = (const float*)d_in[3];
    const float* ema_denom = (const float*)d_in[4];
    float* out = (float*)d_out;
    (void)in_sizes; (void)n_in; (void)out_size;

    cudaFuncSetAttribute(argmin_approx_kernel,
                         cudaFuncAttributeMaxDynamicSharedMemorySize, SMEM_ARG);

    // 1. fused GEMM1 (prep folded in): emb split/norms/zeroing +
    //    transposed fp32/bf16 ze planes + znorm2 partials
    {
        dim3 grid(NN / 128, DDIM / 128, BB);
        gemm1_kernel<<<grid, 256>>>(z, W, emb);
    }

    // 2. Pass A: 3-term approx GEMM + candidate collection
    {
        dim3 grid(NN / 64, BB);
        argmin_approx_kernel<<<grid, 256, SMEM_ARG>>>();
    }

    // 3. Pass B: exact refinement -> g_minidx
    {
        dim3 grid(NN / 8, BB);
        refine_kernel<<<grid, 256>>>(emb);
    }

    // 4. gather zq + scatter EMA statistics
    {
        dim3 grid(NN / 32, BB);
        dim3 blk(32, 8);
        gs_kernel<<<grid, blk>>>(emb, out);
    }

    // 5. EMA blend
    ema_kernel<<<(KKE * DDIM + 255) / 256, 256>>>(ema_numer, ema_denom, out);
}

// round 17
// speedup vs baseline: 1.1256x; 1.0841x over previous
#include <cuda_runtime.h>
#include <cuda_bf16.h>
#include <math_constants.h>
#include <cstdint>

#define BB   8
#define CIN  512
#define NN   4096
#define DDIM 256
#define KKE  2048
#define CAP  16
#define C0_BOUND 1.5e-4f

// ---- scratch (device globals; no allocation allowed) ----
__device__ float g_zet[BB * NN * DDIM];                // ze fp32 transposed [b][n][d]
__device__ float g_esq[KKE];                           // ||e_k||^2
__device__ float g_enorm[KKE];                         // ||e_k||
__device__ float g_znorm2p[2][BB * NN];                // ||ze_n||^2 partials (per d-half)
__device__ int   g_minidx[BB * NN];                    // argmin indices
__device__ float g_zsum[KKE * DDIM];                   // segment sums
__device__ float g_nsum[KKE];                          // segment counts
__device__ __nv_bfloat16 g_embb[2u * KKE * DDIM];      // emb 2-plane bf16 split
__device__ __nv_bfloat16 g_zeb[2u * BB * NN * DDIM];   // ze 2-plane split+transposed
__device__ unsigned int g_cand[(size_t)BB * NN * CAP]; // candidate lists
__device__ unsigned int g_ccnt[BB * NN];               // candidate counts

__device__ __forceinline__ uint32_t smem_u32(const void* p) {
    uint32_t a;
    asm("{ .reg .u64 t; cvta.to.shared.u64 t, %1; cvt.u32.u64 %0, t; }" : "=r"(a) : "l"(p));
    return a;
}
__device__ __forceinline__ void ldsm_x4(uint32_t& r0, uint32_t& r1, uint32_t& r2, uint32_t& r3,
                                        uint32_t addr) {
    asm volatile("ldmatrix.sync.aligned.m8n8.x4.shared.b16 {%0,%1,%2,%3}, [%4];"
                 : "=r"(r0), "=r"(r1), "=r"(r2), "=r"(r3) : "r"(addr));
}
__device__ __forceinline__ void mma16816(float* c, const uint32_t* a, const uint32_t* b) {
    asm volatile("mma.sync.aligned.m16n8k16.row.col.f32.bf16.bf16.f32 "
                 "{%0,%1,%2,%3}, {%4,%5,%6,%7}, {%8,%9}, {%0,%1,%2,%3};"
                 : "+f"(c[0]), "+f"(c[1]), "+f"(c[2]), "+f"(c[3])
                 : "r"(a[0]), "r"(a[1]), "r"(a[2]), "r"(a[3]), "r"(b[0]), "r"(b[1]));
}
__device__ __forceinline__ uint32_t orderable(float s) {
    uint32_t u = __float_as_uint(s);
    return (u & 0x80000000u) ? ~u : (u | 0x80000000u);
}
__device__ __forceinline__ void cp_async16(uint32_t smem_addr, const void* gptr) {
    asm volatile("cp.async.cg.shared.global [%0], [%1], 16;"
                 :: "r"(smem_addr), "l"(gptr) : "memory");
}
#define CP_COMMIT() asm volatile("cp.async.commit_group;" ::: "memory")
#define CP_WAIT0()  asm volatile("cp.async.wait_group 0;" ::: "memory")
// vector float reduction (PTX >= 8.x, sm_90+)
__device__ __forceinline__ void red_add_v4(float* gptr, float x, float y, float z, float w) {
    asm volatile("red.global.add.v4.f32 [%0], {%1, %2, %3, %4};"
                 :: "l"(gptr), "f"(x), "f"(y), "f"(z), "f"(w) : "memory");
}

// ============================================================
// 2-plane bf16 split helper
// ============================================================
__device__ __forceinline__ void split2(float x, __nv_bfloat16& h, __nv_bfloat16& m) {
    h = __float2bfloat16(x);
    m = __float2bfloat16(x - __bfloat162float(h));
}

// ============================================================
// GEMM1 (fused, v3): prep folded into first 256 blocks, then
// ze = W*z -> g_zet/g_zeb + znorm2 partials. (R16 version)
// ============================================================
__global__ void __launch_bounds__(256, 2) gemm1_kernel(
    const float* __restrict__ z, const float* __restrict__ W,
    const float* __restrict__ emb)
{
    __shared__ float Ws[16][132];
    __shared__ float Zs[16][132];
    __shared__ float T[64][129];

    const int n0 = blockIdx.x * 128;
    const int d0 = blockIdx.y * 128;
    const int b  = blockIdx.z;
    const int tid = threadIdx.x;
    const int tk = tid >> 4;
    const int tn = tid & 15;

    // ---- folded prep ----
    {
        const int lb = blockIdx.x + 32 * (blockIdx.y + 2 * blockIdx.z);  // 0..511
        if (lb < 256) {
            const int glb = lb * 256 + tid;          // 0..65535
            const int gw = glb >> 5;                 // code row
            const int lane = tid & 31;

            const float* row = emb + (size_t)gw * DDIM + lane * 8;
            float4 v0 = *(const float4*)row;
            float4 v1 = *(const float4*)(row + 4);
            float s = v0.x*v0.x + v0.y*v0.y + v0.z*v0.z + v0.w*v0.w
                    + v1.x*v1.x + v1.y*v1.y + v1.z*v1.z + v1.w*v1.w;

            float vals[8] = {v0.x, v0.y, v0.z, v0.w, v1.x, v1.y, v1.z, v1.w};
            uint32_t hq[4], mq[4];
#pragma unroll
            for (int p2 = 0; p2 < 4; p2++) {
                __nv_bfloat16 h0, m0, h1, m1;
                split2(vals[p2 * 2], h0, m0);
                split2(vals[p2 * 2 + 1], h1, m1);
                hq[p2] = (uint32_t)__bfloat16_as_ushort(h0) | ((uint32_t)__bfloat16_as_ushort(h1) << 16);
                mq[p2] = (uint32_t)__bfloat16_as_ushort(m0) | ((uint32_t)__bfloat16_as_ushort(m1) << 16);
            }
            const size_t eoff = (size_t)gw * DDIM + lane * 8;
            *(uint4*)&g_embb[eoff] = make_uint4(hq[0], hq[1], hq[2], hq[3]);
            *(uint4*)&g_embb[(size_t)KKE * DDIM + eoff] = make_uint4(mq[0], mq[1], mq[2], mq[3]);

#pragma unroll
            for (int off = 16; off; off >>= 1) s += __shfl_down_sync(0xffffffffu, s, off);
            if (lane == 0) { g_esq[gw] = s; g_enorm[gw] = sqrtf(s); }

            const float4 z4 = make_float4(0.f, 0.f, 0.f, 0.f);
            ((float4*)g_zsum)[glb] = z4;
            ((float4*)g_zsum)[glb + 65536] = z4;
            if (glb < 512) ((float4*)g_nsum)[glb] = z4;
        }
    }

    float acc[8][8];
#pragma unroll
    for (int i = 0; i < 8; i++)
#pragma unroll
        for (int j = 0; j < 8; j++) acc[i][j] = 0.f;

    for (int c0 = 0; c0 < CIN; c0 += 16) {
#pragma unroll
        for (int i = 0; i < 8; i++) {
            int lin = tid + 256 * i;
            int dl = lin >> 4, cc = lin & 15;
            Ws[cc][dl] = W[(size_t)(d0 + dl) * CIN + c0 + cc];
        }
#pragma unroll
        for (int i = 0; i < 8; i++) {
            int lin = tid + 256 * i;
            int cc = lin >> 7, nl = lin & 127;
            Zs[cc][nl] = z[((size_t)b * CIN + c0 + cc) * NN + n0 + nl];
        }
        __syncthreads();
#pragma unroll
        for (int cc = 0; cc < 16; cc++) {
            float4 a0 = *(const float4*)&Ws[cc][tk * 8];
            float4 a1 = *(const float4*)&Ws[cc][tk * 8 + 4];
            float4 b0 = *(const float4*)&Zs[cc][tn * 8];
            float4 b1 = *(const float4*)&Zs[cc][tn * 8 + 4];
            float a[8] = {a0.x, a0.y, a0.z, a0.w, a1.x, a1.y, a1.z, a1.w};
            float bv[8] = {b0.x, b0.y, b0.z, b0.w, b1.x, b1.y, b1.z, b1.w};
#pragma unroll
            for (int i = 0; i < 8; i++)
#pragma unroll
                for (int j = 0; j < 8; j++) acc[i][j] += a[i] * bv[j];
        }
        __syncthreads();
    }

    const int nl  = tid >> 1;
    const int dof = (tid & 1) * 32;
    const size_t ZP = (size_t)BB * NN * DDIM;
    float s2tot = 0.f;

#pragma unroll 1
    for (int p = 0; p < 2; p++) {
        if (p) __syncthreads();
        if ((tk >> 3) == p) {
            const int trow0 = (tk & 7) * 8;
#pragma unroll
            for (int i = 0; i < 8; i++)
#pragma unroll
                for (int j = 0; j < 8; j++)
                    T[trow0 + i][tn * 8 + j] = acc[i][j];
        }
        __syncthreads();

        const size_t base = ((size_t)b * NN + n0 + nl) * DDIM + d0 + p * 64 + dof;
        uint32_t hq[4], mq[4];
#pragma unroll
        for (int u8 = 0; u8 < 8; u8++) {
            float4 f = make_float4(T[dof + u8 * 4 + 0][nl], T[dof + u8 * 4 + 1][nl],
                                   T[dof + u8 * 4 + 2][nl], T[dof + u8 * 4 + 3][nl]);
            *(float4*)&g_zet[base + u8 * 4] = f;
            s2tot = fmaf(f.x, f.x, s2tot); s2tot = fmaf(f.y, f.y, s2tot);
            s2tot = fmaf(f.z, f.z, s2tot); s2tot = fmaf(f.w, f.w, s2tot);
            __nv_bfloat16 h0, m0, h1, m1, h2, m2, h3, m3;
            split2(f.x, h0, m0); split2(f.y, h1, m1);
            split2(f.z, h2, m2); split2(f.w, h3, m3);
            int q = (u8 & 1) * 2;
            hq[q]     = (uint32_t)__bfloat16_as_ushort(h0) | ((uint32_t)__bfloat16_as_ushort(h1) << 16);
            hq[q + 1] = (uint32_t)__bfloat16_as_ushort(h2) | ((uint32_t)__bfloat16_as_ushort(h3) << 16);
            mq[q]     = (uint32_t)__bfloat16_as_ushort(m0) | ((uint32_t)__bfloat16_as_ushort(m1) << 16);
            mq[q + 1] = (uint32_t)__bfloat16_as_ushort(m2) | ((uint32_t)__bfloat16_as_ushort(m3) << 16);
            if (u8 & 1) {
                int e0 = (u8 >> 1) * 8;
                *(uint4*)&g_zeb[base + e0]      = make_uint4(hq[0], hq[1], hq[2], hq[3]);
                *(uint4*)&g_zeb[ZP + base + e0] = make_uint4(mq[0], mq[1], mq[2], mq[3]);
            }
        }
    }
    s2tot += __shfl_xor_sync(0xffffffffu, s2tot, 1);
    if ((tid & 1) == 0)
        g_znorm2p[blockIdx.y][(size_t)b * NN + n0 + nl] = s2tot;
}

// ============================================================
// Pass A: 3-term approx score GEMM + candidate collection.
// (R14/R16 version — unchanged)
// ============================================================
#define STAGE_B  49152
#define OFF_CTRL (2 * STAGE_B)
#define SMEM_ARG (OFF_CTRL + 6144)

__global__ void __launch_bounds__(256, 2) argmin_approx_kernel()
{
    extern __shared__ char smem[];
    unsigned int* colthr  = (unsigned int*)(smem + OFF_CTRL);
    unsigned int* cnt_s   = (unsigned int*)(smem + OFF_CTRL + 256);
    float* znorm_s        = (float*)(smem + OFF_CTRL + 512);
    float* esq_s          = (float*)(smem + OFF_CTRL + 768);
    float* enorm_s        = (float*)(smem + OFF_CTRL + 1280);
    unsigned int* cand_s  = (unsigned int*)(smem + OFF_CTRL + 1792);

    const int tid = threadIdx.x;
    const int wid = tid >> 5;
    const int L   = tid & 31;
    const int n0  = blockIdx.x * 64;
    const int b   = blockIdx.y;
    const int wM  = wid >> 1;
    const int wN  = wid & 1;

    const uint32_t smem_base = smem_u32(smem);
    const size_t ZP = (size_t)BB * NN * DDIM;

    if (tid < 64) {
        colthr[tid] = 0xFFFFFFFFu;
        cnt_s[tid] = 0u;
        const size_t ci = (size_t)b * NN + n0 + tid;
        znorm_s[tid] = sqrtf(g_znorm2p[0][ci] + g_znorm2p[1][ci]);
    }

    const int rowA_l = L & 15;
    const int kxA    = L >> 4;
    const int rowB_l = (L & 7) | ((L & 16) >> 1);
    const int kxB    = (L >> 3) & 1;

    auto load_stage = [&](int s) {
        const int kt = s >> 2, dch = s & 3;
        const int k0 = kt * 128;
        const uint32_t dst = smem_base + (s & 1) * STAGE_B;
#pragma unroll 4
        for (int q = 0; q < 8; q++) {
            int i = tid + 256 * q;
            int p = i >> 10;
            int rem = i & 1023;
            int r = rem >> 3, g = rem & 7;
            const void* src = &g_embb[((size_t)p * KKE + k0 + r) * DDIM + dch * 64 + g * 8];
            cp_async16(dst + p * 16384 + r * 128 + ((g ^ (r & 7)) * 16), src);
        }
#pragma unroll 4
        for (int q = 0; q < 4; q++) {
            int i = tid + 256 * q;
            int p = i >> 9;
            int rem = i & 511;
            int r = rem >> 3, g = rem & 7;
            const void* src = &g_zeb[p * ZP + ((size_t)b * NN + n0 + r) * DDIM + dch * 64 + g * 8];
            cp_async16(dst + 32768 + p * 8192 + r * 128 + ((g ^ (r & 7)) * 16), src);
        }
    };

    load_stage(0);
    CP_COMMIT();

    float acc[2][4][4];

    for (int s = 0; s < 64; s++) {
        const int kt = s >> 2, dch = s & 3;
        const int k0 = kt * 128;

        CP_WAIT0();
        __syncthreads();

        if (s + 1 < 64) { load_stage(s + 1); CP_COMMIT(); }
        if (dch == 0 && tid < 128) {
            esq_s[tid] = g_esq[k0 + tid];
            enorm_s[tid] = g_enorm[k0 + tid];
        }

        if (dch == 0) {
#pragma unroll
            for (int m = 0; m < 2; m++)
#pragma unroll
                for (int j = 0; j < 4; j++)
#pragma unroll
                    for (int r = 0; r < 4; r++) acc[m][j][r] = 0.f;
        }

        const uint32_t buf = smem_base + (s & 1) * STAGE_B;
#pragma unroll
        for (int dc = 0; dc < 4; dc++) {
            uint32_t aH[2][4], aM[2][4], bH[2][4], bM[2][4];
            {
                const int rA0 = wM * 32 + rowA_l;
                const int rA1 = rA0 + 16;
                const int gA  = dc * 2 + kxA;
                const uint32_t swA0 = ((gA ^ (rA0 & 7)) * 16);
                const uint32_t swA1 = ((gA ^ (rA1 & 7)) * 16);
                ldsm_x4(aH[0][0], aH[0][1], aH[0][2], aH[0][3], buf + rA0 * 128 + swA0);
                ldsm_x4(aH[1][0], aH[1][1], aH[1][2], aH[1][3], buf + rA1 * 128 + swA1);
                ldsm_x4(aM[0][0], aM[0][1], aM[0][2], aM[0][3], buf + 16384 + rA0 * 128 + swA0);
                ldsm_x4(aM[1][0], aM[1][1], aM[1][2], aM[1][3], buf + 16384 + rA1 * 128 + swA1);
                const int rB0 = wN * 32 + rowB_l;
                const int rB1 = rB0 + 16;
                const int gB  = dc * 2 + kxB;
                const uint32_t swB0 = ((gB ^ (rB0 & 7)) * 16);
                const uint32_t swB1 = ((gB ^ (rB1 & 7)) * 16);
                ldsm_x4(bH[0][0], bH[0][1], bH[0][2], bH[0][3], buf + 32768 + rB0 * 128 + swB0);
                ldsm_x4(bH[1][0], bH[1][1], bH[1][2], bH[1][3], buf + 32768 + rB1 * 128 + swB1);
                ldsm_x4(bM[0][0], bM[0][1], bM[0][2], bM[0][3], buf + 40960 + rB0 * 128 + swB0);
                ldsm_x4(bM[1][0], bM[1][1], bM[1][2], bM[1][3], buf + 40960 + rB1 * 128 + swB1);
            }
#pragma unroll
            for (int m = 0; m < 2; m++) {      // hh
                mma16816(acc[m][0], aH[m], &bH[0][0]);
                mma16816(acc[m][1], aH[m], &bH[0][2]);
                mma16816(acc[m][2], aH[m], &bH[1][0]);
                mma16816(acc[m][3], aH[m], &bH[1][2]);
            }
#pragma unroll
            for (int m = 0; m < 2; m++) {      // hm
                mma16816(acc[m][0], aH[m], &bM[0][0]);
                mma16816(acc[m][1], aH[m], &bM[0][2]);
                mma16816(acc[m][2], aH[m], &bM[1][0]);
                mma16816(acc[m][3], aH[m], &bM[1][2]);
            }
#pragma unroll
            for (int m = 0; m < 2; m++) {      // mh
                mma16816(acc[m][0], aM[m], &bH[0][0]);
                mma16816(acc[m][1], aM[m], &bH[0][2]);
                mma16816(acc[m][2], aM[m], &bH[1][0]);
                mma16816(acc[m][3], aM[m], &bH[1][2]);
            }
        }

        if (dch == 3) {
            float zn[8];
#pragma unroll
            for (int j = 0; j < 4; j++)
#pragma unroll
                for (int par = 0; par < 2; par++)
                    zn[j * 2 + par] = znorm_s[wN * 32 + j * 8 + (L & 3) * 2 + par];

            uint32_t umin[8];
#pragma unroll
            for (int c = 0; c < 8; c++) umin[c] = 0xFFFFFFFFu;

#pragma unroll
            for (int m = 0; m < 2; m++) {
                const int kl0 = wM * 32 + m * 16 + (L >> 2);
                const int kl1 = kl0 + 8;
                const float e0 = esq_s[kl0], e1 = esq_s[kl1];
                const float en0 = C0_BOUND * enorm_s[kl0], en1 = C0_BOUND * enorm_s[kl1];
#pragma unroll
                for (int j = 0; j < 4; j++)
#pragma unroll
                    for (int r = 0; r < 4; r++) {
                        const int kh = r >> 1, par = r & 1;
                        float sc = fmaf(-2.f, acc[m][j][r], kh ? e1 : e0);
                        acc[m][j][r] = sc;
                        float E = (kh ? en1 : en0) * zn[j * 2 + par];
                        uint32_t u = orderable(sc + E);
                        if (u < umin[j * 2 + par]) umin[j * 2 + par] = u;
                    }
            }
#pragma unroll
            for (int c = 0; c < 8; c++) {
#pragma unroll
                for (int off = 4; off <= 16; off <<= 1) {
                    uint32_t o = __shfl_xor_sync(0xffffffffu, umin[c], off);
                    if (o < umin[c]) umin[c] = o;
                }
            }
            if (L < 4) {
#pragma unroll
                for (int c = 0; c < 8; c++)
                    atomicMin(&colthr[wN * 32 + (c >> 1) * 8 + L * 2 + (c & 1)], umin[c]);
            }
            __syncthreads();

#pragma unroll
            for (int m = 0; m < 2; m++) {
                const int kl0 = wM * 32 + m * 16 + (L >> 2);
                const int kl1 = kl0 + 8;
                const float en0 = C0_BOUND * enorm_s[kl0], en1 = C0_BOUND * enorm_s[kl1];
#pragma unroll
                for (int j = 0; j < 4; j++)
#pragma unroll
                    for (int r = 0; r < 4; r++) {
                        const int kh = r >> 1, par = r & 1;
                        const int col = wN * 32 + j * 8 + (L & 3) * 2 + par;
                        float sc = acc[m][j][r];
                        float E = (kh ? en1 : en0) * zn[j * 2 + par];
                        if (orderable(sc - E) <= colthr[col]) {
                            unsigned pos = atomicAdd(&cnt_s[col], 1u);
                            if (pos < CAP)
                                cand_s[col * CAP + pos] = (unsigned)(k0 + (kh ? kl1 : kl0));
                        }
                    }
            }
        }
    }
    __syncthreads();
    if (tid < 64) g_ccnt[(size_t)b * NN + n0 + tid] = cnt_s[tid];
#pragma unroll
    for (int q = 0; q < 4; q++) {
        int i = tid + 256 * q;
        int lc = i >> 4, slot = i & 15;
        g_cand[((size_t)b * NN + n0 + lc) * CAP + slot] = cand_s[i];
    }
}

// ============================================================
// Pass B: exact fp32 refinement. One warp per column.
// ============================================================
__global__ void refine_kernel(const float* __restrict__ emb) {
    const int wid = threadIdx.x >> 5;
    const int L = threadIdx.x & 31;
    const int n = blockIdx.x * 8 + wid;
    const int b = blockIdx.y;
    const size_t cidx = (size_t)b * NN + n;
    const float* zr = g_zet + cidx * DDIM;

    const float4 z0 = *(const float4*)(zr + L * 8);
    const float4 z1 = *(const float4*)(zr + L * 8 + 4);

    const unsigned cnt = g_ccnt[cidx];
    unsigned long long best = 0xFFFFFFFFFFFFFFFFull;

    if (cnt <= CAP) {
        for (unsigned i = 0; i < cnt; i++) {
            const unsigned k = g_cand[cidx * CAP + i];
            const float* er = emb + (size_t)k * DDIM;
            float4 e0 = *(const float4*)(er + L * 8);
            float4 e1 = *(const float4*)(er + L * 8 + 4);
            float d = e0.x*z0.x;
            d = fmaf(e0.y, z0.y, d); d = fmaf(e0.z, z0.z, d); d = fmaf(e0.w, z0.w, d);
            d = fmaf(e1.x, z1.x, d); d = fmaf(e1.y, z1.y, d);
            d = fmaf(e1.z, z1.z, d); d = fmaf(e1.w, z1.w, d);
#pragma unroll
            for (int off = 16; off; off >>= 1) d += __shfl_xor_sync(0xffffffffu, d, off);
            float s = fmaf(-2.f, d, g_esq[k]);
            unsigned long long pk = ((unsigned long long)orderable(s) << 32) | k;
            if (pk < best) best = pk;
        }
    } else {
        for (int k = L; k < KKE; k += 32) {
            const float* er = emb + (size_t)k * DDIM;
            float d = 0.f;
#pragma unroll 8
            for (int v = 0; v < 64; v++) {
                float4 e4 = *(const float4*)(er + v * 4);
                float4 z4 = *(const float4*)(zr + v * 4);
                d = fmaf(e4.x, z4.x, d); d = fmaf(e4.y, z4.y, d);
                d = fmaf(e4.z, z4.z, d); d = fmaf(e4.w, z4.w, d);
            }
            float s = fmaf(-2.f, d, g_esq[k]);
            unsigned long long pk = ((unsigned long long)orderable(s) << 32) | (unsigned)k;
            if (pk < best) best = pk;
        }
#pragma unroll
        for (int off = 16; off; off >>= 1) {
            unsigned long long o = __shfl_xor_sync(0xffffffffu, best, off);
            if (o < best) best = o;
        }
    }
    if (L == 0) g_minidx[cidx] = (int)(best & 0xFFFFFFFFull);
}

// ============================================================
// gather zq -> out, scatter-add ze into z_sum / n_sum.
// v2: vector red.global.add.v4.f32 (4x fewer atomic ops).
// block (32, 8): tx = column, ty covers 8 d-groups of 4.
// ============================================================
__global__ void gs_kernel(const float* __restrict__ emb, float* __restrict__ out)
{
    __shared__ float zs[32][257];
    const int b  = blockIdx.y;
    const int n0 = blockIdx.x * 32;
    const int tx = threadIdx.x;
    const int ty = threadIdx.y;
    const int tid = ty * 32 + tx;

#pragma unroll
    for (int q = 0; q < 8; q++) {
        int i = tid + 256 * q;
        int r = i >> 6, c4 = i & 63;
        float4 v = *(const float4*)&g_zet[((size_t)b * NN + n0 + r) * DDIM + c4 * 4];
        zs[r][c4 * 4 + 0] = v.x; zs[r][c4 * 4 + 1] = v.y;
        zs[r][c4 * 4 + 2] = v.z; zs[r][c4 * 4 + 3] = v.w;
    }
    __syncthreads();

    const int n = n0 + tx;
    const int idx = g_minidx[(size_t)b * NN + n];
    const float* erow = emb + (size_t)idx * DDIM;
#pragma unroll
    for (int g = 0; g < 8; g++) {
        const int d4 = (g * 8 + ty) * 4;
        // gather: coalesced out stores (consecutive tx -> consecutive n)
        float4 e4 = *(const float4*)(erow + d4);
        out[((size_t)b * DDIM + d4 + 0) * NN + n] = e4.x;
        out[((size_t)b * DDIM + d4 + 1) * NN + n] = e4.y;
        out[((size_t)b * DDIM + d4 + 2) * NN + n] = e4.z;
        out[((size_t)b * DDIM + d4 + 3) * NN + n] = e4.w;
        // scatter: one vector reduction for 4 adds
        red_add_v4(&g_zsum[(size_t)idx * DDIM + d4],
                   zs[tx][d4 + 0], zs[tx][d4 + 1], zs[tx][d4 + 2], zs[tx][d4 + 3]);
    }
    if (ty == 0) atomicAdd(&g_nsum[idx], 1.0f);
}

// ============================================================
// EMA finalize -> tail of d_out
// ============================================================
__global__ void ema_kernel(const float* __restrict__ ema_numer,
                           const float* __restrict__ ema_denom,
                           float* __restrict__ out)
{
    const size_t OUT_OFF = (size_t)BB * DDIM * NN;
    int i = blockIdx.x * blockDim.x + threadIdx.x;
    if (i < KKE * DDIM)
        out[OUT_OFF + i] = 0.99f * ema_numer[i] + 0.01f * g_zsum[i];
    if (i < KKE)
        out[OUT_OFF + (size_t)KKE * DDIM + i] = 0.99f * ema_denom[i] + 0.01f * g_nsum[i];
}

// ============================================================
extern "C" void kernel_launch(void* const* d_in, const int* in_sizes, int n_in,
                              void* d_out, int out_size)
{
    const float* z         = (const float*)d_in[0];
    const float* W         = (const float*)d_in[1];
    const float* emb       = (const float*)d_in[2];
    const float* ema_numer = (const float*)d_in[3];
    const float* ema_denom = (const float*)d_in[4];
    float* out = (float*)d_out;
    (void)in_sizes; (void)n_in; (void)out_size;

    cudaFuncSetAttribute(argmin_approx_kernel,
                         cudaFuncAttributeMaxDynamicSharedMemorySize, SMEM_ARG);

    // 1. fused GEMM1 (prep folded in)
    {
        dim3 grid(NN / 128, DDIM / 128, BB);
        gemm1_kernel<<<grid, 256>>>(z, W, emb);
    }

    // 2. Pass A: 3-term approx GEMM + candidate collection
    {
        dim3 grid(NN / 64, BB);
        argmin_approx_kernel<<<grid, 256, SMEM_ARG>>>();
    }

    // 3. Pass B: exact refinement -> g_minidx
    {
        dim3 grid(NN / 8, BB);
        refine_kernel<<<grid, 256>>>(emb);
    }

    // 4. gather zq + scatter EMA statistics (vector reductions)
    {
        dim3 grid(NN / 32, BB);
        dim3 blk(32, 8);
        gs_kernel<<<grid, blk>>>(emb, out);
    }

    // 5. EMA blend
    ema_kernel<<<(KKE * DDIM + 255) / 256, 256>>>(ema_numer, ema_denom, out);
}